// round 6
// baseline (speedup 1.0000x reference)
#include <cuda_runtime.h>
#include <cuda_bf16.h>
#include <cuda_fp16.h>
#include <cstdint>

// ---------------------------------------------------------------------------
// EdgeClassNet: node MLP (fp32 FFMA2) + fused 9-layer edge MLP on warp-level
// fp16 mma.sync. R6: 2 CTAs/SM (128 thr, 64 edges) to overlap epilogues and
// syncs across CTAs; per-chunk B-fragment preload to hide LDSM latency.
// ---------------------------------------------------------------------------

constexpr int DN   = 256;   // node input dim
constexpr int IN   = 128;   // node hidden dim
constexpr int EA   = 16;
constexpr int NOUT = 3;
constexpr int TMN  = 64;    // node kernel tile
constexpr int KCN  = 16;

constexpr int MAXN = 65536;
constexpr int MAXE = 262144;

// 73 weight chunks: layer0 = 9 chunks of K<=32, layers 1..8 = 8 chunks each.
// Each chunk image: [256 n][40 k] fp16 = 20480 B.
constexpr int NCHUNK = 73;
constexpr int WCH    = 20480;
constexpr int RING   = 3;

__device__ float g_hnode[MAXN * IN];
__device__ int   g_ei[2 * MAXE];
__device__ int   g_is64;
__device__ __align__(16) unsigned char g_wpack[NCHUNK * WCH];

// ======================= small utility kernels =============================
__global__ void detect_kernel(const int* __restrict__ ei_raw) {
    __shared__ int cnt;
    if (threadIdx.x == 0) cnt = 0;
    __syncthreads();
    if (ei_raw[2 * threadIdx.x + 1] != 0) atomicAdd(&cnt, 1);
    __syncthreads();
    if (threadIdx.x == 0) g_is64 = (cnt == 0) ? 1 : 0;
}
__global__ void convert_kernel(const int* __restrict__ ei_raw, int n2e) {
    int i = blockIdx.x * blockDim.x + threadIdx.x;
    if (i >= n2e) return;
    g_ei[i] = g_is64 ? ei_raw[2 * i] : ei_raw[i];
}
// pack weights into per-chunk SMEM images (transposed to [n][k], fp16)
__global__ void prep_pack(const float* __restrict__ W0,
                          const float* __restrict__ Wmid) {
    int idx = blockIdx.x * 256 + threadIdx.x;       // over 73*256*40
    if (idx >= NCHUNK * 256 * 40) return;
    int klocal = idx % 40;
    int n  = (idx / 40) & 255;
    int ch = idx / (40 * 256);
    int L, cc;
    if (ch < 9) { L = 0; cc = ch; } else { L = 1 + (ch - 9) / 8; cc = (ch - 9) & 7; }
    int k = cc * 32 + klocal;
    int K = (L == 0) ? 272 : 256;
    float w = 0.f;
    if (klocal < 32 && k < K)
        w = (L == 0) ? W0[k * 256 + n] : Wmid[(L - 1) * 65536 + k * 256 + n];
    *(__half*)(g_wpack + (size_t)ch * WCH + n * 80 + klocal * 2) = __float2half_rn(w);
}

// ======================= PTX helpers =======================================
__device__ __forceinline__ uint32_t smem_u32(const void* p) {
    uint32_t a;
    asm("{ .reg .u64 t; cvta.to.shared.u64 t, %1; cvt.u32.u64 %0, t; }"
        : "=r"(a) : "l"(p));
    return a;
}
__device__ __forceinline__ void cp16b(char* dst, const char* src) {
    unsigned u = (unsigned)__cvta_generic_to_shared(dst);
    asm volatile("cp.async.cg.shared.global [%0], [%1], 16;" :: "r"(u), "l"(src));
}
__device__ __forceinline__ void cp_commit() { asm volatile("cp.async.commit_group;"); }
template<int N> __device__ __forceinline__ void cp_wait() {
    asm volatile("cp.async.wait_group %0;" :: "n"(N));
}
__device__ __forceinline__ void mbar_init(uint32_t a, uint32_t cnt) {
    asm volatile("mbarrier.init.shared.b64 [%0], %1;" :: "r"(a), "r"(cnt) : "memory");
}
__device__ __forceinline__ void mbar_expect_tx(uint32_t a, uint32_t bytes) {
    asm volatile("mbarrier.arrive.expect_tx.shared.b64 _, [%0], %1;"
                 :: "r"(a), "r"(bytes) : "memory");
}
__device__ __forceinline__ void bulk_g2s(uint32_t dst, const void* src,
                                         uint32_t bytes, uint32_t mbar) {
    asm volatile(
        "cp.async.bulk.shared::cluster.global.mbarrier::complete_tx::bytes "
        "[%0], [%1], %2, [%3];"
        :: "r"(dst), "l"(src), "r"(bytes), "r"(mbar) : "memory");
}
__device__ __forceinline__ void mbar_wait(uint32_t mbar, uint32_t parity) {
    asm volatile(
        "{\n\t.reg .pred P1;\n\t"
        "WAIT_LOOP_%=:\n\t"
        "mbarrier.try_wait.parity.acquire.cta.shared::cta.b64 P1, [%0], %1, 0x989680;\n\t"
        "@P1 bra.uni WAIT_DONE_%=;\n\t"
        "bra.uni WAIT_LOOP_%=;\n\t"
        "WAIT_DONE_%=:\n\t}"
        :: "r"(mbar), "r"(parity) : "memory");
}
__device__ __forceinline__ void ldm_x4(uint32_t* r, uint32_t addr) {
    asm volatile("ldmatrix.sync.aligned.m8n8.x4.shared.b16 {%0,%1,%2,%3}, [%4];"
                 : "=r"(r[0]), "=r"(r[1]), "=r"(r[2]), "=r"(r[3]) : "r"(addr));
}
__device__ __forceinline__ void mma16816(float* c, const uint32_t* a,
                                         uint32_t b0, uint32_t b1) {
    asm volatile(
        "mma.sync.aligned.m16n8k16.row.col.f32.f16.f16.f32 "
        "{%0,%1,%2,%3}, {%4,%5,%6,%7}, {%8,%9}, {%0,%1,%2,%3};"
        : "+f"(c[0]), "+f"(c[1]), "+f"(c[2]), "+f"(c[3])
        : "r"(a[0]), "r"(a[1]), "r"(a[2]), "r"(a[3]), "r"(b0), "r"(b1));
}
__device__ __forceinline__ uint32_t h2(float v0, float v1) {
    __half2 h = __floats2half2_rn(v0, v1);
    return *(uint32_t*)&h;
}

// ======================= node MLP (FFMA2 path, known good) =================
__device__ __forceinline__ unsigned long long pack2(float x) {
    unsigned long long r; unsigned v = __float_as_uint(x);
    asm("mov.b64 %0, {%1,%2};" : "=l"(r) : "r"(v), "r"(v));
    return r;
}
__device__ __forceinline__ void ffma2(unsigned long long& c, unsigned long long a,
                                      unsigned long long b) {
    asm("fma.rn.f32x2 %0, %1, %2, %0;" : "+l"(c) : "l"(a), "l"(b));
}
__device__ __forceinline__ float2 unpack2(unsigned long long v) {
    unsigned lo, hi;
    asm("mov.b64 {%0,%1}, %2;" : "=r"(lo), "=r"(hi) : "l"(v));
    float2 f; f.x = __uint_as_float(lo); f.y = __uint_as_float(hi);
    return f;
}
__device__ __forceinline__ void cp16f(float* dst, const float* src) {
    cp16b((char*)dst, (const char*)src);
}

constexpr int XSTR   = 260;
constexpr int A_SMEM = (TMN * XSTR + 2 * KCN * IN) * 4;

__global__ void __launch_bounds__(256, 2)
node_mlp_kernel(const float* __restrict__ x, const float* __restrict__ Wx,
                const float* __restrict__ bx)
{
    extern __shared__ float sm[];
    float* abuf = sm;
    float* bbuf = sm + TMN * XSTR;
    const int tid = threadIdx.x;
    const long long r0 = (long long)blockIdx.x * TMN;
    {
        int e = tid >> 2, q = tid & 3;
        const float* src = x + (r0 + e) * DN + q * 64;
        float* dst = abuf + e * XSTR + q * 64;
#pragma unroll
        for (int i = 0; i < 16; i++) cp16f(dst + i * 4, src + i * 4);
        cp_commit();
    }
    const int tr = tid >> 4, tc = tid & 15;
    const int m0 = tr * 4;
    unsigned long long acc[4][4];
#pragma unroll
    for (int i = 0; i < 4; i++)
#pragma unroll
        for (int j = 0; j < 4; j++) acc[i][j] = 0ull;
    constexpr int CHUNK = KCN * IN;
    {
#pragma unroll
        for (int i = 0; i < 2; i++)
            cp16f(bbuf + (tid + i * 256) * 4, Wx + (tid + i * 256) * 4);
        cp_commit();
    }
    const int nk = DN / KCN;
    for (int kc = 0; kc < nk; kc++) {
        if (kc + 1 < nk) {
            const float* src = Wx + (long long)(kc + 1) * CHUNK;
            float* dst = bbuf + ((kc + 1) & 1) * CHUNK;
#pragma unroll
            for (int i = 0; i < 2; i++)
                cp16f(dst + (tid + i * 256) * 4, src + (tid + i * 256) * 4);
            cp_commit();
            cp_wait<1>();
        } else cp_wait<0>();
        __syncthreads();
        const float* Bs = bbuf + (kc & 1) * CHUNK;
        const float* As = abuf + kc * KCN;
#pragma unroll
        for (int kk = 0; kk < KCN; kk++) {
            unsigned long long breg[4];
            const float* brow = Bs + kk * IN + 2 * tc;
#pragma unroll
            for (int j = 0; j < 4; j++)
                breg[j] = *(const unsigned long long*)(brow + 32 * j);
#pragma unroll
            for (int i = 0; i < 4; i++) {
                unsigned long long aa = pack2(As[(m0 + i) * XSTR + kk]);
#pragma unroll
                for (int j = 0; j < 4; j++) ffma2(acc[i][j], aa, breg[j]);
            }
        }
        __syncthreads();
    }
    float* gout = g_hnode + r0 * IN;
#pragma unroll
    for (int i = 0; i < 4; i++)
#pragma unroll
        for (int j = 0; j < 4; j++) {
            int n = 2 * tc + 32 * j;
            float2 v = unpack2(acc[i][j]);
            v.x += bx[n]; v.y += bx[n + 1];
            v.x = fmaxf(v.x, 0.01f * v.x);
            v.y = fmaxf(v.y, 0.01f * v.y);
            *(float2*)(gout + (long long)(m0 + i) * IN + n) = v;
        }
}

// ======================= edge MLP on fp16 mma.sync (2 CTA/SM) ==============
constexpr int ASTRB  = 560;                      // A row stride: 280 fp16
constexpr int OFF_W  = 64 * ASTRB;               // 35840 (ring of 3 chunk bufs)
constexpr int OFF_PT = OFF_W;                    // classifier partials (reuse)
constexpr int OFF_MB = OFF_W + RING * WCH;       // 97280 (3 mbarriers)
constexpr int SMEM_E = OFF_MB + 64;              // 97344

__global__ void __launch_bounds__(128, 2)
edge_hmma_kernel(const float* __restrict__ eattr,
                 const float* __restrict__ b0, const float* __restrict__ bmid,
                 const float* __restrict__ Wlast, const float* __restrict__ blast,
                 float* __restrict__ out, int E)
{
    extern __shared__ char smc[];
    const uint32_t sbase = smem_u32(smc);
    const int tid = threadIdx.x, wid = tid >> 5, lane = tid & 31;
    const int CB = 64 * wid;                      // 1 x 4 warp grid, 64 rows each
    const long long e0 = (long long)blockIdx.x * 64;

    if (tid == 0)
        for (int i = 0; i < RING; i++) mbar_init(sbase + OFF_MB + i * 8, 1);
    __syncthreads();
    if (tid == 0) {
        for (int ci = 0; ci < RING; ci++) {
            uint32_t mb = sbase + OFF_MB + ci * 8;
            mbar_expect_tx(mb, WCH);
            bulk_g2s(sbase + OFF_W + ci * WCH, g_wpack + (size_t)ci * WCH, WCH, mb);
        }
    }

    // ---------------- gather ef -> A plane (fp16) ---------------------------
    {
        int e = tid >> 1, half = tid & 1;
        long long ge = e0 + e;
        int ridx = g_ei[ge];
        int cidx = g_ei[(long long)E + ge];
        const float4* hr4 = (const float4*)(g_hnode + (long long)ridx * IN);
        const float4* hc4 = (const float4*)(g_hnode + (long long)cidx * IN);
        const float4* ea4 = (const float4*)(eattr + ge * EA);
        int ch = half * 136;
#pragma unroll 2
        for (int g = 0; g < 34; g++) {
            int c = ch + 4 * g;
            float4 f = (c < 128) ? hr4[c >> 2]
                     : (c < 256) ? hc4[(c - 128) >> 2]
                                 : ea4[(c - 256) >> 2];
            char* pA = smc + e * ASTRB + c * 2;
            *(uint32_t*)(pA)     = h2(f.x, f.y);
            *(uint32_t*)(pA + 4) = h2(f.z, f.w);
        }
    }
    __syncthreads();

    // ---------------- per-thread invariant addresses ------------------------
    const int i7 = lane & 7;
    const int rowOff  = ((lane >> 3) & 1) * 8 + i7;
    const int aColOff = (lane >= 16) ? 16 : 0;            // bytes
    uint32_t aB[4];
#pragma unroll
    for (int i = 0; i < 4; i++)
        aB[i] = sbase + (uint32_t)(16 * i + rowOff) * ASTRB + aColOff;
    const int nIdx  = CB + ((lane >= 16) ? 8 : 0) + i7;
    const int bkOff = ((lane >> 3) & 1) * 16;             // bytes
    uint32_t bB[4];
#pragma unroll
    for (int j = 0; j < 4; j++) bB[j] = (uint32_t)(nIdx + 16 * j) * 80 + bkOff;

    float c[4][8][4];
#pragma unroll
    for (int i = 0; i < 4; i++)
#pragma unroll
        for (int j = 0; j < 8; j++)
#pragma unroll
            for (int q = 0; q < 4; q++) c[i][j][q] = 0.f;

    int chunkIdx = 0, buf = 0, ph = 0;

#pragma unroll 1
    for (int L = 0; L < 9; L++) {
        const int nch = (L == 0) ? 9 : 8;
#pragma unroll 1
        for (int cI = 0; cI < nch; cI++) {
            mbar_wait(sbase + OFF_MB + buf * 8, ph);
            const uint32_t wb = sbase + OFF_W + buf * WCH;
            const int twoSteps = !(L == 0 && cI == 8);
            const int kbB = cI * 64;                       // A byte offset of chunk
            // preload all B fragments of the chunk (both k16 steps)
            uint32_t b[2][4][4];
#pragma unroll
            for (int j = 0; j < 4; j++) ldm_x4(b[0][j], wb + bB[j]);
            if (twoSteps) {
#pragma unroll
                for (int j = 0; j < 4; j++) ldm_x4(b[1][j], wb + bB[j] + 32);
            }
#pragma unroll 1
            for (int s = 0; s < 1 + twoSteps; s++) {
                uint32_t a[4][4];
#pragma unroll
                for (int i = 0; i < 4; i++) ldm_x4(a[i], aB[i] + kbB + s * 32);
#pragma unroll
                for (int i = 0; i < 4; i++)
#pragma unroll
                    for (int j = 0; j < 4; j++) {
                        mma16816(c[i][2 * j],     a[i], b[s][j][0], b[s][j][1]);
                        mma16816(c[i][2 * j + 1], a[i], b[s][j][2], b[s][j][3]);
                    }
            }
            __syncthreads();
            if (tid == 0 && chunkIdx + RING < NCHUNK) {
                const uint32_t mb2 = sbase + OFF_MB + buf * 8;
                mbar_expect_tx(mb2, WCH);
                bulk_g2s(sbase + OFF_W + buf * WCH,
                         g_wpack + (size_t)(chunkIdx + RING) * WCH, WCH, mb2);
            }
            chunkIdx++;
            if (++buf == RING) { buf = 0; ph ^= 1; }
        }

        if (L < 8) {
            // epilogue: leaky(D + bias) -> fp16 -> A plane; zero C
            const float* bias = (L == 0) ? b0 : bmid + (L - 1) * 256;
#pragma unroll
            for (int i = 0; i < 4; i++) {
                const int row0 = 16 * i + (lane >> 2);
#pragma unroll
                for (int j = 0; j < 8; j++) {
                    const int col = CB + 8 * j + 2 * (lane & 3);
                    float2 bb = __ldg((const float2*)(bias + col));
                    float v0 = c[i][j][0] + bb.x, v1 = c[i][j][1] + bb.y;
                    float v2 = c[i][j][2] + bb.x, v3 = c[i][j][3] + bb.y;
                    v0 = fmaxf(v0, 0.01f * v0); v1 = fmaxf(v1, 0.01f * v1);
                    v2 = fmaxf(v2, 0.01f * v2); v3 = fmaxf(v3, 0.01f * v3);
                    char* p0 = smc + row0 * ASTRB + col * 2;
                    *(uint32_t*)(p0)             = h2(v0, v1);
                    *(uint32_t*)(p0 + 8 * ASTRB) = h2(v2, v3);
                    c[i][j][0] = 0.f; c[i][j][1] = 0.f;
                    c[i][j][2] = 0.f; c[i][j][3] = 0.f;
                }
            }
            __syncthreads();
        }
    }

    // ---------------- classifier + log_softmax ------------------------------
    {
        const float* bias = bmid + 7 * 256;
        float p[4][2][3];
#pragma unroll
        for (int i = 0; i < 4; i++)
#pragma unroll
            for (int h = 0; h < 2; h++)
                p[i][h][0] = p[i][h][1] = p[i][h][2] = 0.f;
#pragma unroll
        for (int i = 0; i < 4; i++) {
#pragma unroll
            for (int j = 0; j < 8; j++) {
                const int col = CB + 8 * j + 2 * (lane & 3);
                float2 bb = __ldg((const float2*)(bias + col));
                float v0 = c[i][j][0] + bb.x, v1 = c[i][j][1] + bb.y;
                float v2 = c[i][j][2] + bb.x, v3 = c[i][j][3] + bb.y;
                v0 = fmaxf(v0, 0.01f * v0); v1 = fmaxf(v1, 0.01f * v1);
                v2 = fmaxf(v2, 0.01f * v2); v3 = fmaxf(v3, 0.01f * v3);
                const float* w0 = Wlast + col * 3;
#pragma unroll
                for (int k = 0; k < 3; k++) {
                    float wa = __ldg(w0 + k), wb2 = __ldg(w0 + 3 + k);
                    p[i][0][k] = fmaf(v0, wa, fmaf(v1, wb2, p[i][0][k]));
                    p[i][1][k] = fmaf(v2, wa, fmaf(v3, wb2, p[i][1][k]));
                }
            }
        }
#pragma unroll
        for (int i = 0; i < 4; i++)
#pragma unroll
            for (int h = 0; h < 2; h++)
#pragma unroll
                for (int k = 0; k < 3; k++) {
                    float v = p[i][h][k];
                    v += __shfl_xor_sync(0xffffffffu, v, 1);
                    v += __shfl_xor_sync(0xffffffffu, v, 2);
                    p[i][h][k] = v;
                }
        float* pt = (float*)(smc + OFF_PT);   // [64 rows][4 wid][3]
        if ((lane & 3) == 0) {
#pragma unroll
            for (int i = 0; i < 4; i++)
#pragma unroll
                for (int h = 0; h < 2; h++) {
                    int row = 16 * i + (lane >> 2) + 8 * h;
#pragma unroll
                    for (int k = 0; k < 3; k++)
                        pt[(row * 4 + wid) * 3 + k] = p[i][h][k];
                }
        }
    }
    __syncthreads();
    if (tid < 64) {
        const float* pt = (const float*)(smc + OFF_PT);
        float l[3];
#pragma unroll
        for (int k = 0; k < 3; k++) {
            float s = __ldg(blast + k);
#pragma unroll
            for (int g = 0; g < 4; g++) s += pt[(tid * 4 + g) * 3 + k];
            l[k] = s;
        }
        float mx  = fmaxf(l[0], fmaxf(l[1], l[2]));
        float lse = mx + logf(expf(l[0] - mx) + expf(l[1] - mx) + expf(l[2] - mx));
        float* o = out + (e0 + tid) * NOUT;
        o[0] = l[0] - lse; o[1] = l[1] - lse; o[2] = l[2] - lse;
    }
}

// ===========================================================================
extern "C" void kernel_launch(void* const* d_in, const int* in_sizes, int n_in,
                              void* d_out, int out_size)
{
    const float* x      = (const float*)d_in[0];
    const int*   ei_raw = (const int*)d_in[1];
    const float* eattr  = (const float*)d_in[2];
    const float* Wx     = (const float*)d_in[3];
    const float* bx     = (const float*)d_in[4];
    const float* W0     = (const float*)d_in[5];
    const float* b0     = (const float*)d_in[6];
    const float* Wmid   = (const float*)d_in[7];
    const float* bmid   = (const float*)d_in[8];
    const float* Wlast  = (const float*)d_in[9];
    const float* blast  = (const float*)d_in[10];
    float* out = (float*)d_out;

    const int N  = in_sizes[0] / DN;
    const int E  = in_sizes[2] / EA;
    const int n2 = 2 * E;

    cudaFuncSetAttribute(node_mlp_kernel,
                         cudaFuncAttributeMaxDynamicSharedMemorySize, A_SMEM);
    cudaFuncSetAttribute(edge_hmma_kernel,
                         cudaFuncAttributeMaxDynamicSharedMemorySize, SMEM_E);

    detect_kernel<<<1, 256>>>(ei_raw);
    convert_kernel<<<(n2 + 255) / 256, 256>>>(ei_raw, n2);
    prep_pack<<<(NCHUNK * 256 * 40 + 255) / 256, 256>>>(W0, Wmid);
    node_mlp_kernel<<<N / TMN, 256, A_SMEM>>>(x, Wx, bx);
    edge_hmma_kernel<<<E / 64, 128, SMEM_E>>>(eattr, b0, bmid, Wlast, blast,
                                              out, E);
}